// round 2
// baseline (speedup 1.0000x reference)
#include <cuda_runtime.h>
#include <cstdint>
#include <math.h>

// Problem constants (static shapes from reference)
#define T_TOK 16384     // G*S = 4*4096
#define NE    8         // experts
#define DD    1024      // model dim
#define HH    4096      // hidden dim
#define CAP   2048      // capacity per expert

// ---------------- scratch (static device allocations; no cudaMalloc) ----------------
__device__ float g_probs[T_TOK * NE];                     // 512 KB
__device__ int   g_idx[NE * CAP];                         // 64 KB
__device__ float g_score[NE * CAP];                       // 64 KB
__device__ float g_H[(size_t)T_TOK * HH];                 // 256 MB, reused shared->routed

// ---------------- helpers ----------------
__device__ __forceinline__ float to_tf32(float x) {
    float y;
    asm("cvt.rna.tf32.f32 %0, %1;" : "=f"(y) : "f"(x));
    return y;
}

__device__ __forceinline__ float gelu_f(float x) {
    // JAX approximate gelu: 0.5*x*(1+tanh(sqrt(2/pi)*(x+0.044715*x^3)))
    float x3 = x * x * x;
    return 0.5f * x * (1.0f + tanhf(0.7978845608028654f * (x + 0.044715f * x3)));
}

// ---------------- router: logits + softmax ----------------
// one warp per token; 8 warps/block
__global__ __launch_bounds__(256) void router_kernel(
    const float* __restrict__ x, const float* __restrict__ gate,
    float* __restrict__ probs)
{
    int lane = threadIdx.x & 31;
    int warp = threadIdx.x >> 5;
    int t = blockIdx.x * 8 + warp;
    if (t >= T_TOK) return;
    const float* xr = x + (size_t)t * DD;

    float acc[NE];
#pragma unroll
    for (int e = 0; e < NE; e++) acc[e] = 0.f;

#pragma unroll
    for (int i = 0; i < DD / 128; i++) {
        int d = i * 128 + lane * 4;
        float4 xv = *reinterpret_cast<const float4*>(xr + d);
#pragma unroll
        for (int r = 0; r < 4; r++) {
            float xs = (&xv.x)[r];
            float4 g0 = *reinterpret_cast<const float4*>(gate + (size_t)(d + r) * NE);
            float4 g1 = *reinterpret_cast<const float4*>(gate + (size_t)(d + r) * NE + 4);
            acc[0] += xs * g0.x; acc[1] += xs * g0.y; acc[2] += xs * g0.z; acc[3] += xs * g0.w;
            acc[4] += xs * g1.x; acc[5] += xs * g1.y; acc[6] += xs * g1.z; acc[7] += xs * g1.w;
        }
    }
#pragma unroll
    for (int e = 0; e < NE; e++) {
#pragma unroll
        for (int o = 16; o > 0; o >>= 1)
            acc[e] += __shfl_xor_sync(0xffffffffu, acc[e], o);
    }
    float mx = acc[0];
#pragma unroll
    for (int e = 1; e < NE; e++) mx = fmaxf(mx, acc[e]);
    float ex[NE];
    float s = 0.f;
#pragma unroll
    for (int e = 0; e < NE; e++) { ex[e] = expf(acc[e] - mx); s += ex[e]; }
    float inv = 1.0f / s;
    if (lane < NE) probs[(size_t)t * NE + lane] = ex[lane] * inv;
}

// ---------------- exact top-2048 per expert (64-bit radix select) ----------------
// key = (float_bits(prob) << 32) | (0xFFFFFFFF - token)  -> top-k by value, ties -> lowest index
// Keys held in registers across all 8 radix passes (one gmem read per element total).
__global__ __launch_bounds__(1024) void topk_kernel(
    const float* __restrict__ probs, int* __restrict__ topk_idx,
    float* __restrict__ topk_score)
{
    constexpr int PER = T_TOK / 1024;   // 16
    int e = blockIdx.x;
    __shared__ unsigned int hist[256];
    __shared__ unsigned long long s_prefix;
    __shared__ unsigned int s_k;
    __shared__ unsigned int s_count;

    unsigned long long keys[PER];
#pragma unroll
    for (int i = 0; i < PER; i++) {
        int t = threadIdx.x + i * 1024;
        float p = probs[(size_t)t * NE + e];
        keys[i] = ((unsigned long long)__float_as_uint(p) << 32) |
                  (unsigned long long)(0xFFFFFFFFu - (unsigned)t);
    }

    if (threadIdx.x == 0) { s_prefix = 0ULL; s_k = CAP; s_count = 0; }
    __syncthreads();

    for (int bp = 7; bp >= 0; bp--) {
        if (threadIdx.x < 256) hist[threadIdx.x] = 0;
        __syncthreads();
        unsigned long long prefix = s_prefix;
        int shift = bp * 8;
        unsigned long long prefmask = (bp == 7) ? 0ULL : ((~0ULL) << (shift + 8));
#pragma unroll
        for (int i = 0; i < PER; i++) {
            if ((keys[i] & prefmask) == (prefix & prefmask))
                atomicAdd(&hist[(unsigned)((keys[i] >> shift) & 255ULL)], 1u);
        }
        __syncthreads();
        if (threadIdx.x == 0) {
            unsigned int k = s_k, cum = 0;
            int b;
            for (b = 255; b >= 0; b--) {
                if (cum + hist[b] >= k) break;
                cum += hist[b];
            }
            s_prefix = prefix | ((unsigned long long)(unsigned)b << shift);
            s_k = k - cum;
        }
        __syncthreads();
    }
    unsigned long long pivot = s_prefix;
#pragma unroll
    for (int i = 0; i < PER; i++) {
        if (keys[i] >= pivot) {
            unsigned int pos = atomicAdd(&s_count, 1u);
            if (pos < CAP) {
                topk_idx[e * CAP + pos] = (int)(0xFFFFFFFFu - (unsigned)(keys[i] & 0xFFFFFFFFULL));
                topk_score[e * CAP + pos] = __uint_as_float((unsigned)(keys[i] >> 32));
            }
        }
    }
}

// ---------------- tf32 mma.sync GEMM with fused gather / gelu / scatter ----------------
// Double-buffered smem, register-prefetch pipeline, one __syncthreads per k-tile.
// C[m][n] = act( sum_k A[row(m)][k] * W[g][k][n] + bias[g][n] )
//   GELU   : apply gelu epilogue (layer 1)
//   ATOMIC : out[scatter[m]][n] += C*scores[m]  (routed layer 2)
//   else   : out[g*M + m][n] = C               (H buffer / shared layer 2)
#define BM 128
#define BN 64
#define BK 32
#define A_STRIDE (BK + 4)            // 36: A frag loads conflict-free
#define B_STRIDE (BN + 4)            // 68: B frag loads 2-way (was 72 -> 8-way!)
#define A_TILE (BM * A_STRIDE)       // 4608 floats
#define B_TILE (BK * B_STRIDE)       // 2176 floats
#define GEMM_SMEM_BYTES ((2 * A_TILE + 2 * B_TILE) * 4)   // 54272 B

template <bool GELU, bool ATOMIC>
__global__ __launch_bounds__(256) void gemm_tf32(
    const float* __restrict__ A, size_t a_gstride,
    const int* __restrict__ gather, int lda,
    const float* __restrict__ W, const float* __restrict__ bias,
    float* __restrict__ Out, int ldo,
    const int* __restrict__ scatter, const float* __restrict__ scores,
    int M, int N, int K)
{
    extern __shared__ float smem[];   // [As0 | As1 | Bs0 | Bs1]

    int g = blockIdx.z;
    const float* Ag = A + (size_t)g * a_gstride;
    const float* Wg = W + (size_t)g * (size_t)K * N;
    const float* bg = bias + (size_t)g * N;
    const int* gatherg = gather ? (gather + (size_t)g * M) : nullptr;

    int tid = threadIdx.x;
    int lane = tid & 31, warp = tid >> 5;
    int warpM = warp & 3, warpN = warp >> 2;     // 4 x 2 warp grid, 32x32 warp tile
    int mBase = blockIdx.y * BM, nBase = blockIdx.x * BN;

    // A staging: 32 rows x 8 float4-slots per pass, 4 passes (with row gather)
    int ar = tid >> 3;   // 0..31
    int aq = tid & 7;    // float4 slot within 32-wide k chunk
    const float* arow_ptr[4];
#pragma unroll
    for (int p = 0; p < 4; p++) {
        int m = mBase + p * 32 + ar;
        int grow = gatherg ? gatherg[m] : m;
        arow_ptr[p] = Ag + (size_t)grow * lda + (aq << 2);
    }
    // B staging: 16 float4 per 64-wide row, 32 rows via 2 passes of 16
    int bq = tid & 15, bk = tid >> 4;
    const float* bptr0 = Wg + (size_t)bk * N + nBase + (bq << 2);

    float acc[2][4][4];
#pragma unroll
    for (int i = 0; i < 2; i++)
#pragma unroll
        for (int j = 0; j < 4; j++)
#pragma unroll
            for (int v = 0; v < 4; v++) acc[i][j][v] = 0.f;

    int r = lane >> 2, c = lane & 3;

    float4 aPre[4], bPre[2];
    // prologue: load k-tile 0
#pragma unroll
    for (int p = 0; p < 4; p++)
        aPre[p] = *reinterpret_cast<const float4*>(arow_ptr[p]);
#pragma unroll
    for (int p = 0; p < 2; p++)
        bPre[p] = *reinterpret_cast<const float4*>(bptr0 + (size_t)(p * 16) * N);
    // store to buffer 0 (tf32-round while staging)
    {
        float* As = smem;
        float* Bs = smem + 2 * A_TILE;
#pragma unroll
        for (int p = 0; p < 4; p++) {
            float4 v = aPre[p];
            v.x = to_tf32(v.x); v.y = to_tf32(v.y); v.z = to_tf32(v.z); v.w = to_tf32(v.w);
            *reinterpret_cast<float4*>(&As[(p * 32 + ar) * A_STRIDE + (aq << 2)]) = v;
        }
#pragma unroll
        for (int p = 0; p < 2; p++) {
            float4 v = bPre[p];
            v.x = to_tf32(v.x); v.y = to_tf32(v.y); v.z = to_tf32(v.z); v.w = to_tf32(v.w);
            *reinterpret_cast<float4*>(&Bs[(p * 16 + bk) * B_STRIDE + (bq << 2)]) = v;
        }
    }
    __syncthreads();

    int kIters = K / BK;
    for (int kt = 0; kt < kIters; kt++) {
        int buf = kt & 1;
        // prefetch next k-tile into registers (latency hidden by MMA below)
        if (kt + 1 < kIters) {
            int k0 = (kt + 1) * BK;
#pragma unroll
            for (int p = 0; p < 4; p++)
                aPre[p] = *reinterpret_cast<const float4*>(arow_ptr[p] + k0);
#pragma unroll
            for (int p = 0; p < 2; p++)
                bPre[p] = *reinterpret_cast<const float4*>(bptr0 + (size_t)(k0 + p * 16) * N);
        }

        // compute on current buffer
        {
            const float* As = smem + buf * A_TILE;
            const float* Bs = smem + 2 * A_TILE + buf * B_TILE;
#pragma unroll
            for (int ks = 0; ks < 4; ks++) {
                unsigned afr[2][4], bfr[4][2];
#pragma unroll
                for (int i = 0; i < 2; i++) {
                    int m0 = warpM * 32 + i * 16 + r;
                    afr[i][0] = __float_as_uint(As[(m0    ) * A_STRIDE + ks * 8 + c    ]);
                    afr[i][1] = __float_as_uint(As[(m0 + 8) * A_STRIDE + ks * 8 + c    ]);
                    afr[i][2] = __float_as_uint(As[(m0    ) * A_STRIDE + ks * 8 + c + 4]);
                    afr[i][3] = __float_as_uint(As[(m0 + 8) * A_STRIDE + ks * 8 + c + 4]);
                }
#pragma unroll
                for (int j = 0; j < 4; j++) {
                    int n0 = warpN * 32 + j * 8 + r;
                    bfr[j][0] = __float_as_uint(Bs[(ks * 8 + c    ) * B_STRIDE + n0]);
                    bfr[j][1] = __float_as_uint(Bs[(ks * 8 + c + 4) * B_STRIDE + n0]);
                }
#pragma unroll
                for (int i = 0; i < 2; i++)
#pragma unroll
                    for (int j = 0; j < 4; j++)
                        asm volatile(
                            "mma.sync.aligned.m16n8k8.row.col.f32.tf32.tf32.f32 "
                            "{%0,%1,%2,%3}, {%4,%5,%6,%7}, {%8,%9}, {%0,%1,%2,%3};"
                            : "+f"(acc[i][j][0]), "+f"(acc[i][j][1]),
                              "+f"(acc[i][j][2]), "+f"(acc[i][j][3])
                            : "r"(afr[i][0]), "r"(afr[i][1]), "r"(afr[i][2]), "r"(afr[i][3]),
                              "r"(bfr[j][0]), "r"(bfr[j][1]));
            }
        }

        // store prefetched tile into the other buffer (free since end of kt-1)
        if (kt + 1 < kIters) {
            float* As = smem + (buf ^ 1) * A_TILE;
            float* Bs = smem + 2 * A_TILE + (buf ^ 1) * B_TILE;
#pragma unroll
            for (int p = 0; p < 4; p++) {
                float4 v = aPre[p];
                v.x = to_tf32(v.x); v.y = to_tf32(v.y); v.z = to_tf32(v.z); v.w = to_tf32(v.w);
                *reinterpret_cast<float4*>(&As[(p * 32 + ar) * A_STRIDE + (aq << 2)]) = v;
            }
#pragma unroll
            for (int p = 0; p < 2; p++) {
                float4 v = bPre[p];
                v.x = to_tf32(v.x); v.y = to_tf32(v.y); v.z = to_tf32(v.z); v.w = to_tf32(v.w);
                *reinterpret_cast<float4*>(&Bs[(p * 16 + bk) * B_STRIDE + (bq << 2)]) = v;
            }
        }
        __syncthreads();
    }

    // epilogue
#pragma unroll
    for (int i = 0; i < 2; i++) {
#pragma unroll
        for (int v2 = 0; v2 < 2; v2++) {
            int m = mBase + warpM * 32 + i * 16 + r + v2 * 8;
            int tokRow = 0; float sc = 0.f;
            if (ATOMIC) {
                tokRow = scatter[(size_t)g * M + m];
                sc = scores[(size_t)g * M + m];
            }
#pragma unroll
            for (int j = 0; j < 4; j++) {
#pragma unroll
                for (int v1 = 0; v1 < 2; v1++) {
                    int n = nBase + warpN * 32 + j * 8 + c * 2 + v1;
                    float v = acc[i][j][v2 * 2 + v1] + bg[n];
                    if (GELU) v = gelu_f(v);
                    if (ATOMIC) {
                        atomicAdd(Out + (size_t)tokRow * ldo + n, v * sc);
                    } else {
                        Out[(size_t)g * (size_t)M * ldo + (size_t)m * ldo + n] = v;
                    }
                }
            }
        }
    }
}

// ---------------- launch ----------------
extern "C" void kernel_launch(void* const* d_in, const int* in_sizes, int n_in,
                              void* d_out, int out_size)
{
    const float* x    = (const float*)d_in[0];
    const float* gate = (const float*)d_in[1];
    const float* W1   = (const float*)d_in[2];
    const float* b1   = (const float*)d_in[3];
    const float* W2   = (const float*)d_in[4];
    const float* b2   = (const float*)d_in[5];
    const float* Ws1  = (const float*)d_in[6];
    const float* bs1  = (const float*)d_in[7];
    const float* Ws2  = (const float*)d_in[8];
    const float* bs2  = (const float*)d_in[9];
    float* out = (float*)d_out;

    float* probs;  cudaGetSymbolAddress((void**)&probs,  g_probs);
    int*   idx;    cudaGetSymbolAddress((void**)&idx,    g_idx);
    float* score;  cudaGetSymbolAddress((void**)&score,  g_score);
    float* H;      cudaGetSymbolAddress((void**)&H,      g_H);

    // opt-in to >48KB dynamic smem (host-side attribute set; capture-safe)
    cudaFuncSetAttribute((const void*)gemm_tf32<true,  false>,
                         cudaFuncAttributeMaxDynamicSharedMemorySize, GEMM_SMEM_BYTES);
    cudaFuncSetAttribute((const void*)gemm_tf32<false, false>,
                         cudaFuncAttributeMaxDynamicSharedMemorySize, GEMM_SMEM_BYTES);
    cudaFuncSetAttribute((const void*)gemm_tf32<false, true>,
                         cudaFuncAttributeMaxDynamicSharedMemorySize, GEMM_SMEM_BYTES);

    // 1) router + exact top-k
    router_kernel<<<T_TOK / 8, 256>>>(x, gate, probs);
    topk_kernel<<<NE, 1024>>>(probs, idx, score);

    // 2) shared expert: gelu(x @ Ws1 + bs1) @ Ws2 + bs2 -> plain store covers all of out
    gemm_tf32<true, false><<<dim3(HH / 64, T_TOK / 128, 1), 256, GEMM_SMEM_BYTES>>>(
        x, 0, nullptr, DD, Ws1, bs1, H, HH, nullptr, nullptr, T_TOK, HH, DD);
    gemm_tf32<false, false><<<dim3(DD / 64, T_TOK / 128, 1), 256, GEMM_SMEM_BYTES>>>(
        H, 0, nullptr, HH, Ws2, bs2, out, DD, nullptr, nullptr, T_TOK, DD, HH);

    // 3) routed experts: gather -> FFN -> scaled atomic scatter-add (after shared store)
    gemm_tf32<true, false><<<dim3(HH / 64, CAP / 128, NE), 256, GEMM_SMEM_BYTES>>>(
        x, 0, idx, DD, W1, b1, H, HH, nullptr, nullptr, CAP, HH, DD);
    gemm_tf32<false, true><<<dim3(DD / 64, CAP / 128, NE), 256, GEMM_SMEM_BYTES>>>(
        H, (size_t)CAP * HH, nullptr, HH, W2, b2, out, DD, idx, score, CAP, DD, HH);
}

// round 3
// speedup vs baseline: 1.2148x; 1.2148x over previous
#include <cuda_runtime.h>
#include <cstdint>
#include <math.h>

// Problem constants (static shapes from reference)
#define T_TOK 16384     // G*S = 4*4096
#define NE    8         // experts
#define DD    1024      // model dim
#define HH    4096      // hidden dim
#define CAP   2048      // capacity per expert

// ---------------- scratch (static device allocations; no cudaMalloc) ----------------
__device__ float g_probs[T_TOK * NE];                     // 512 KB
__device__ int   g_idx[NE * CAP];                         // 64 KB
__device__ float g_score[NE * CAP];                       // 64 KB
__device__ float g_H[(size_t)T_TOK * HH];                 // 256 MB, reused shared->routed

// ---------------- helpers ----------------
__device__ __forceinline__ float to_tf32(float x) {
    float y;
    asm("cvt.rna.tf32.f32 %0, %1;" : "=f"(y) : "f"(x));
    return y;
}

__device__ __forceinline__ float gelu_f(float x) {
    // JAX approximate gelu: 0.5*x*(1+tanh(sqrt(2/pi)*(x+0.044715*x^3)))
    float x3 = x * x * x;
    return 0.5f * x * (1.0f + tanhf(0.7978845608028654f * (x + 0.044715f * x3)));
}

// ---------------- router: logits + softmax ----------------
__global__ __launch_bounds__(256) void router_kernel(
    const float* __restrict__ x, const float* __restrict__ gate,
    float* __restrict__ probs)
{
    int lane = threadIdx.x & 31;
    int warp = threadIdx.x >> 5;
    int t = blockIdx.x * 8 + warp;
    if (t >= T_TOK) return;
    const float* xr = x + (size_t)t * DD;

    float acc[NE];
#pragma unroll
    for (int e = 0; e < NE; e++) acc[e] = 0.f;

#pragma unroll
    for (int i = 0; i < DD / 128; i++) {
        int d = i * 128 + lane * 4;
        float4 xv = *reinterpret_cast<const float4*>(xr + d);
#pragma unroll
        for (int r = 0; r < 4; r++) {
            float xs = (&xv.x)[r];
            float4 g0 = *reinterpret_cast<const float4*>(gate + (size_t)(d + r) * NE);
            float4 g1 = *reinterpret_cast<const float4*>(gate + (size_t)(d + r) * NE + 4);
            acc[0] += xs * g0.x; acc[1] += xs * g0.y; acc[2] += xs * g0.z; acc[3] += xs * g0.w;
            acc[4] += xs * g1.x; acc[5] += xs * g1.y; acc[6] += xs * g1.z; acc[7] += xs * g1.w;
        }
    }
#pragma unroll
    for (int e = 0; e < NE; e++) {
#pragma unroll
        for (int o = 16; o > 0; o >>= 1)
            acc[e] += __shfl_xor_sync(0xffffffffu, acc[e], o);
    }
    float mx = acc[0];
#pragma unroll
    for (int e = 1; e < NE; e++) mx = fmaxf(mx, acc[e]);
    float ex[NE];
    float s = 0.f;
#pragma unroll
    for (int e = 0; e < NE; e++) { ex[e] = expf(acc[e] - mx); s += ex[e]; }
    float inv = 1.0f / s;
    if (lane < NE) probs[(size_t)t * NE + lane] = ex[lane] * inv;
}

// ---------------- exact top-2048 per expert (64-bit radix select) ----------------
__global__ __launch_bounds__(1024) void topk_kernel(
    const float* __restrict__ probs, int* __restrict__ topk_idx,
    float* __restrict__ topk_score)
{
    constexpr int PER = T_TOK / 1024;   // 16
    int e = blockIdx.x;
    __shared__ unsigned int hist[256];
    __shared__ unsigned long long s_prefix;
    __shared__ unsigned int s_k;
    __shared__ unsigned int s_count;

    unsigned long long keys[PER];
#pragma unroll
    for (int i = 0; i < PER; i++) {
        int t = threadIdx.x + i * 1024;
        float p = probs[(size_t)t * NE + e];
        keys[i] = ((unsigned long long)__float_as_uint(p) << 32) |
                  (unsigned long long)(0xFFFFFFFFu - (unsigned)t);
    }

    if (threadIdx.x == 0) { s_prefix = 0ULL; s_k = CAP; s_count = 0; }
    __syncthreads();

    for (int bp = 7; bp >= 0; bp--) {
        if (threadIdx.x < 256) hist[threadIdx.x] = 0;
        __syncthreads();
        unsigned long long prefix = s_prefix;
        int shift = bp * 8;
        unsigned long long prefmask = (bp == 7) ? 0ULL : ((~0ULL) << (shift + 8));
#pragma unroll
        for (int i = 0; i < PER; i++) {
            if ((keys[i] & prefmask) == (prefix & prefmask))
                atomicAdd(&hist[(unsigned)((keys[i] >> shift) & 255ULL)], 1u);
        }
        __syncthreads();
        if (threadIdx.x == 0) {
            unsigned int k = s_k, cum = 0;
            int b;
            for (b = 255; b >= 0; b--) {
                if (cum + hist[b] >= k) break;
                cum += hist[b];
            }
            s_prefix = prefix | ((unsigned long long)(unsigned)b << shift);
            s_k = k - cum;
        }
        __syncthreads();
    }
    unsigned long long pivot = s_prefix;
#pragma unroll
    for (int i = 0; i < PER; i++) {
        if (keys[i] >= pivot) {
            unsigned int pos = atomicAdd(&s_count, 1u);
            if (pos < CAP) {
                topk_idx[e * CAP + pos] = (int)(0xFFFFFFFFu - (unsigned)(keys[i] & 0xFFFFFFFFULL));
                topk_score[e * CAP + pos] = __uint_as_float((unsigned)(keys[i] >> 32));
            }
        }
    }
}

// ---------------- tf32 mma.sync GEMM, 128x128 block, 32x64 warp tile ----------------
// Double-buffered smem, register-prefetch pipeline, one __syncthreads per k-tile.
//   GELU   : apply gelu epilogue (layer 1)
//   ATOMIC : out[scatter[m]][n] += C*scores[m]  (routed layer 2)
//   else   : out[g*M + m][n] = C
#define BM 128
#define BN 128
#define BK 32
#define A_STRIDE (BK + 4)            // 36: bank = 4r+c  -> conflict-free
#define B_STRIDE (BN + 8)            // 136 ≡ 8 (mod 32): bank = 8(c+j)+r -> conflict-free
#define A_TILE (BM * A_STRIDE)       // 4608 floats
#define B_TILE (BK * B_STRIDE)       // 4352 floats
#define GEMM_SMEM_BYTES ((2 * A_TILE + 2 * B_TILE) * 4)   // 71680 B

template <bool GELU, bool ATOMIC>
__global__ __launch_bounds__(256, 1) void gemm_tf32(
    const float* __restrict__ A, size_t a_gstride,
    const int* __restrict__ gather, int lda,
    const float* __restrict__ W, const float* __restrict__ bias,
    float* __restrict__ Out, int ldo,
    const int* __restrict__ scatter, const float* __restrict__ scores,
    int M, int N, int K)
{
    extern __shared__ float smem[];   // [As0 | As1 | Bs0 | Bs1]

    int g = blockIdx.z;
    const float* Ag = A + (size_t)g * a_gstride;
    const float* Wg = W + (size_t)g * (size_t)K * N;
    const float* bg = bias + (size_t)g * N;
    const int* gatherg = gather ? (gather + (size_t)g * M) : nullptr;

    int tid = threadIdx.x;
    int lane = tid & 31, warp = tid >> 5;
    int warpM = warp & 3, warpN = warp >> 2;     // 4 x 2 warp grid, 32x64 warp tile
    int mBase = blockIdx.y * BM, nBase = blockIdx.x * BN;

    // A staging: 32 rows x 8 float4-slots per pass, 4 passes (with row gather)
    int ar = tid >> 3;   // 0..31
    int aq = tid & 7;    // float4 slot within 32-wide k chunk
    const float* arow_ptr[4];
#pragma unroll
    for (int p = 0; p < 4; p++) {
        int m = mBase + p * 32 + ar;
        int grow = gatherg ? gatherg[m] : m;
        arow_ptr[p] = Ag + (size_t)grow * lda + (aq << 2);
    }
    // B staging: 32 float4 per 128-wide row, 8 rows per pass, 4 passes
    int bq = tid & 31, bk = tid >> 5;
    const float* bptr0 = Wg + (size_t)bk * N + nBase + (bq << 2);

    float acc[2][8][4];
#pragma unroll
    for (int i = 0; i < 2; i++)
#pragma unroll
        for (int j = 0; j < 8; j++)
#pragma unroll
            for (int v = 0; v < 4; v++) acc[i][j][v] = 0.f;

    int r = lane >> 2, c = lane & 3;

    float4 aPre[4], bPre[4];
    // prologue: load k-tile 0
#pragma unroll
    for (int p = 0; p < 4; p++)
        aPre[p] = *reinterpret_cast<const float4*>(arow_ptr[p]);
#pragma unroll
    for (int p = 0; p < 4; p++)
        bPre[p] = *reinterpret_cast<const float4*>(bptr0 + (size_t)(p * 8) * N);
    {
        float* As = smem;
        float* Bs = smem + 2 * A_TILE;
#pragma unroll
        for (int p = 0; p < 4; p++) {
            float4 v = aPre[p];
            v.x = to_tf32(v.x); v.y = to_tf32(v.y); v.z = to_tf32(v.z); v.w = to_tf32(v.w);
            *reinterpret_cast<float4*>(&As[(p * 32 + ar) * A_STRIDE + (aq << 2)]) = v;
        }
#pragma unroll
        for (int p = 0; p < 4; p++) {
            float4 v = bPre[p];
            v.x = to_tf32(v.x); v.y = to_tf32(v.y); v.z = to_tf32(v.z); v.w = to_tf32(v.w);
            *reinterpret_cast<float4*>(&Bs[(p * 8 + bk) * B_STRIDE + (bq << 2)]) = v;
        }
    }
    __syncthreads();

    int kIters = K / BK;
    for (int kt = 0; kt < kIters; kt++) {
        int buf = kt & 1;
        // prefetch next k-tile into registers (latency hidden by MMAs below)
        if (kt + 1 < kIters) {
            int k0 = (kt + 1) * BK;
#pragma unroll
            for (int p = 0; p < 4; p++)
                aPre[p] = *reinterpret_cast<const float4*>(arow_ptr[p] + k0);
#pragma unroll
            for (int p = 0; p < 4; p++)
                bPre[p] = *reinterpret_cast<const float4*>(bptr0 + (size_t)(k0 + p * 8) * N);
        }

        // compute on current buffer
        {
            const float* As = smem + buf * A_TILE;
            const float* Bs = smem + 2 * A_TILE + buf * B_TILE;
#pragma unroll
            for (int ks = 0; ks < 4; ks++) {
                unsigned afr[2][4], bfr[8][2];
#pragma unroll
                for (int i = 0; i < 2; i++) {
                    int m0 = warpM * 32 + i * 16 + r;
                    afr[i][0] = __float_as_uint(As[(m0    ) * A_STRIDE + ks * 8 + c    ]);
                    afr[i][1] = __float_as_uint(As[(m0 + 8) * A_STRIDE + ks * 8 + c    ]);
                    afr[i][2] = __float_as_uint(As[(m0    ) * A_STRIDE + ks * 8 + c + 4]);
                    afr[i][3] = __float_as_uint(As[(m0 + 8) * A_STRIDE + ks * 8 + c + 4]);
                }
#pragma unroll
                for (int j = 0; j < 8; j++) {
                    int n0 = warpN * 64 + j * 8 + r;
                    bfr[j][0] = __float_as_uint(Bs[(ks * 8 + c    ) * B_STRIDE + n0]);
                    bfr[j][1] = __float_as_uint(Bs[(ks * 8 + c + 4) * B_STRIDE + n0]);
                }
#pragma unroll
                for (int i = 0; i < 2; i++)
#pragma unroll
                    for (int j = 0; j < 8; j++)
                        asm volatile(
                            "mma.sync.aligned.m16n8k8.row.col.f32.tf32.tf32.f32 "
                            "{%0,%1,%2,%3}, {%4,%5,%6,%7}, {%8,%9}, {%0,%1,%2,%3};"
                            : "+f"(acc[i][j][0]), "+f"(acc[i][j][1]),
                              "+f"(acc[i][j][2]), "+f"(acc[i][j][3])
                            : "r"(afr[i][0]), "r"(afr[i][1]), "r"(afr[i][2]), "r"(afr[i][3]),
                              "r"(bfr[j][0]), "r"(bfr[j][1]));
            }
        }

        // store prefetched tile into the other buffer
        if (kt + 1 < kIters) {
            float* As = smem + (buf ^ 1) * A_TILE;
            float* Bs = smem + 2 * A_TILE + (buf ^ 1) * B_TILE;
#pragma unroll
            for (int p = 0; p < 4; p++) {
                float4 v = aPre[p];
                v.x = to_tf32(v.x); v.y = to_tf32(v.y); v.z = to_tf32(v.z); v.w = to_tf32(v.w);
                *reinterpret_cast<float4*>(&As[(p * 32 + ar) * A_STRIDE + (aq << 2)]) = v;
            }
#pragma unroll
            for (int p = 0; p < 4; p++) {
                float4 v = bPre[p];
                v.x = to_tf32(v.x); v.y = to_tf32(v.y); v.z = to_tf32(v.z); v.w = to_tf32(v.w);
                *reinterpret_cast<float4*>(&Bs[(p * 8 + bk) * B_STRIDE + (bq << 2)]) = v;
            }
        }
        __syncthreads();
    }

    // epilogue
#pragma unroll
    for (int i = 0; i < 2; i++) {
#pragma unroll
        for (int v2 = 0; v2 < 2; v2++) {
            int m = mBase + warpM * 32 + i * 16 + r + v2 * 8;
            int tokRow = 0; float sc = 0.f;
            if (ATOMIC) {
                tokRow = scatter[(size_t)g * M + m];
                sc = scores[(size_t)g * M + m];
            }
#pragma unroll
            for (int j = 0; j < 8; j++) {
#pragma unroll
                for (int v1 = 0; v1 < 2; v1++) {
                    int n = nBase + warpN * 64 + j * 8 + c * 2 + v1;
                    float v = acc[i][j][v2 * 2 + v1] + bg[n];
                    if (GELU) v = gelu_f(v);
                    if (ATOMIC) {
                        atomicAdd(Out + (size_t)tokRow * ldo + n, v * sc);
                    } else {
                        Out[(size_t)g * (size_t)M * ldo + (size_t)m * ldo + n] = v;
                    }
                }
            }
        }
    }
}

// ---------------- launch ----------------
extern "C" void kernel_launch(void* const* d_in, const int* in_sizes, int n_in,
                              void* d_out, int out_size)
{
    const float* x    = (const float*)d_in[0];
    const float* gate = (const float*)d_in[1];
    const float* W1   = (const float*)d_in[2];
    const float* b1   = (const float*)d_in[3];
    const float* W2   = (const float*)d_in[4];
    const float* b2   = (const float*)d_in[5];
    const float* Ws1  = (const float*)d_in[6];
    const float* bs1  = (const float*)d_in[7];
    const float* Ws2  = (const float*)d_in[8];
    const float* bs2  = (const float*)d_in[9];
    float* out = (float*)d_out;

    float* probs;  cudaGetSymbolAddress((void**)&probs,  g_probs);
    int*   idx;    cudaGetSymbolAddress((void**)&idx,    g_idx);
    float* score;  cudaGetSymbolAddress((void**)&score,  g_score);
    float* H;      cudaGetSymbolAddress((void**)&H,      g_H);

    cudaFuncSetAttribute((const void*)gemm_tf32<true,  false>,
                         cudaFuncAttributeMaxDynamicSharedMemorySize, GEMM_SMEM_BYTES);
    cudaFuncSetAttribute((const void*)gemm_tf32<false, false>,
                         cudaFuncAttributeMaxDynamicSharedMemorySize, GEMM_SMEM_BYTES);
    cudaFuncSetAttribute((const void*)gemm_tf32<false, true>,
                         cudaFuncAttributeMaxDynamicSharedMemorySize, GEMM_SMEM_BYTES);

    // 1) router + exact top-k
    router_kernel<<<T_TOK / 8, 256>>>(x, gate, probs);
    topk_kernel<<<NE, 1024>>>(probs, idx, score);

    // 2) shared expert: gelu(x @ Ws1 + bs1) @ Ws2 + bs2 -> plain store covers all of out
    gemm_tf32<true, false><<<dim3(HH / BN, T_TOK / BM, 1), 256, GEMM_SMEM_BYTES>>>(
        x, 0, nullptr, DD, Ws1, bs1, H, HH, nullptr, nullptr, T_TOK, HH, DD);
    gemm_tf32<false, false><<<dim3(DD / BN, T_TOK / BM, 1), 256, GEMM_SMEM_BYTES>>>(
        H, 0, nullptr, HH, Ws2, bs2, out, DD, nullptr, nullptr, T_TOK, DD, HH);

    // 3) routed experts: gather -> FFN -> scaled atomic scatter-add (after shared store)
    gemm_tf32<true, false><<<dim3(HH / BN, CAP / BM, NE), 256, GEMM_SMEM_BYTES>>>(
        x, 0, idx, DD, W1, b1, H, HH, nullptr, nullptr, CAP, HH, DD);
    gemm_tf32<false, true><<<dim3(DD / BN, CAP / BM, NE), 256, GEMM_SMEM_BYTES>>>(
        H, (size_t)CAP * HH, nullptr, HH, W2, b2, out, DD, idx, score, CAP, DD, HH);
}